// round 9
// baseline (speedup 1.0000x reference)
#include <cuda_runtime.h>

// VariantCoeLinear1d: 1D Rusanov FV solver, 128 rows x 2048 pts x 256 steps.
// One CTA per row (128 CTAs, single wave). 512 threads x 4 register points.
//
// R9 = R7 + TWO-STEP TEMPORAL FUSION via 2-wide ghost zones: each thread
// reads 2 ghost u's per side (scalar-pair LDS from double-buffered SMEM),
// advances step A on 8 points -> u' on 6 points (with mid-fusion outflow BC
// at the global edges), then step B -> u'' on its 4 owned points. ONE
// barrier and ONE halo exchange per TWO steps, amortizing the ~140cyc/step
// serial overhead (BAR + LDS->poly chain) that capped R7. 255 steps =
// 127 fused iterations + 1 single tail step. Both frames streamed per iter.

#define BATCH 128
#define NPTS  2048
#define STEPS 256
#define TPB   512
#define PPT   4   // TPB*PPT == NPTS

typedef unsigned long long u64;

static __device__ __forceinline__ u64 pk(float lo, float hi) {
    u64 r; asm("mov.b64 %0,{%1,%2};" : "=l"(r) : "f"(lo), "f"(hi)); return r;
}
static __device__ __forceinline__ void upk(float& lo, float& hi, u64 v) {
    asm("mov.b64 {%0,%1},%2;" : "=f"(lo), "=f"(hi) : "l"(v));
}
static __device__ __forceinline__ u64 f2fma(u64 a, u64 b, u64 c) {
    u64 d; asm("fma.rn.f32x2 %0,%1,%2,%3;" : "=l"(d) : "l"(a), "l"(b), "l"(c)); return d;
}
static __device__ __forceinline__ u64 f2mul(u64 a, u64 b) {
    u64 d; asm("mul.rn.f32x2 %0,%1,%2;" : "=l"(d) : "l"(a), "l"(b)); return d;
}

// fh = (f_l + f_r) - max(a_l,a_r) * (u_r - u_l)   (0.5 folded into HL)
static __device__ __forceinline__ float iface(float ul, float fl, float al,
                                              float ur, float fr, float ar) {
    float am = fmaxf(al, ar);
    return fmaf(-am, ur - ul, fl + fr);
}

// Horner pack: f and |f'| for two points, 10 f32x2 ops.
#define POLY_PACK(U, FLO, FHI, ALO, AHI)                                   \
    do {                                                                   \
        u64 _u2 = f2mul(U, U);                                             \
        u64 _t  = f2fma(CB6, _u2, CB4);                                    \
        _t      = f2fma(_t, U, CB3);                                       \
        _t      = f2fma(_t, U, CB2);                                       \
        _t      = f2fma(_t, U, CB1);                                       \
        u64 _F  = f2mul(_t, U);                                            \
        u64 _s  = f2fma(CA5, _u2, CA3);                                    \
        _s      = f2fma(_s, U, CA2);                                       \
        _s      = f2fma(_s, U, CA1);                                       \
        _s      = f2fma(_s, U, CA0);                                       \
        u64 _A  = _s & ABSM;                                               \
        upk(FLO, FHI, _F);                                                 \
        upk(ALO, AHI, _A);                                                 \
    } while (0)

__global__ void __launch_bounds__(TPB, 1)
vcl_kernel(const float* __restrict__ init, float* __restrict__ out)
{
    // double-buffered boundary PAIRS (u only)
    __shared__ float2 sL[2][TPB];   // thread t's first two points  (x0, x1)
    __shared__ float2 sR[2][TPB];   // thread t's last two points   (x2, x3)

    const int row  = blockIdx.x;
    const int tid  = threadIdx.x;
    const int base = tid * PPT;
    const int tl   = (tid > 0) ? tid - 1 : 0;              // edge dummies:
    const int tr   = (tid < TPB - 1) ? tid + 1 : TPB - 1;  // overwritten by BC
    const bool e0  = (tid == 0);
    const bool e1  = (tid == TPB - 1);
    const float HL = 0.5f * (float)(0.002 / (10.0 / 2048.0));  // 0.5*dt/dx

    const double c = 0.1 / 12.0;   // beta/12
    const u64 CB1 = pk(1.5f, 1.5f);
    const u64 CB2 = pk((float)(0.75 * c),        (float)(0.75 * c));
    const u64 CB3 = pk((float)(-0.5 - 2.0 * c),  (float)(-0.5 - 2.0 * c));
    const u64 CB4 = pk((float)(1.5 * c),         (float)(1.5 * c));
    const u64 CB6 = pk((float)(-0.25 * c),       (float)(-0.25 * c));
    const u64 CA0 = pk(1.5f, 1.5f);
    const u64 CA1 = pk((float)(1.5 * c),         (float)(1.5 * c));
    const u64 CA2 = pk((float)(-1.5 - 6.0 * c),  (float)(-1.5 - 6.0 * c));
    const u64 CA3 = pk((float)(6.0 * c),         (float)(6.0 * c));
    const u64 CA5 = pk((float)(-1.5 * c),        (float)(-1.5 * c));
    const u64 ABSM = 0x7fffffff7fffffffULL;

    float u0, u1, u2, u3;
    {
        const float4* ip = reinterpret_cast<const float4*>(init + (size_t)row * NPTS + base);
        float4 a0 = ip[0];
        u0 = a0.x; u1 = a0.y; u2 = a0.z; u3 = a0.w;
        float4* o0 = reinterpret_cast<float4*>(out + (size_t)row * NPTS + base);
        __stcs(o0, a0);
    }
    sL[0][tid] = make_float2(u0, u1);
    sR[0][tid] = make_float2(u2, u3);

    float4* op = reinterpret_cast<float4*>(out + ((size_t)BATCH + row) * NPTS + base);
    const size_t ostride = (size_t)BATCH * NPTS / 4;

    int p = 0;
    #pragma unroll 1
    for (int it = 0; it < 127; ++it) {   // steps 2it+1 and 2it+2  (1..254)
        __syncthreads();
        float2 lg = sR[p][tl];   // u(base-2), u(base-1)
        float2 rg = sL[p][tr];   // u(base+4), u(base+5)

        // ========== step A: f,|f'| on 8 points (4 packs) ==========
        float fL0, fL1, aL0, aL1, f0, f1, a0, a1, f2, f3, a2, a3, fR0, fR1, aR0, aR1;
        { u64 U = pk(lg.x, lg.y); POLY_PACK(U, fL0, fL1, aL0, aL1); }
        { u64 U = pk(u0, u1);     POLY_PACK(U, f0, f1, a0, a1); }
        { u64 U = pk(u2, u3);     POLY_PACK(U, f2, f3, a2, a3); }
        { u64 U = pk(rg.x, rg.y); POLY_PACK(U, fR0, fR1, aR0, aR1); }

        float hm2 = iface(lg.x, fL0, aL0, lg.y, fL1, aL1);   // (-2,-1)
        float hm1 = iface(lg.y, fL1, aL1, u0, f0, a0);       // (-1, 0)
        float h0  = iface(u0, f0, a0, u1, f1, a1);
        float h1  = iface(u1, f1, a1, u2, f2, a2);
        float h2  = iface(u2, f2, a2, u3, f3, a3);
        float h3  = iface(u3, f3, a3, rg.x, fR0, aR0);       // (3, 4)
        float h4  = iface(rg.x, fR0, aR0, rg.y, fR1, aR1);   // (4, 5)

        float vm1 = fmaf(-HL, hm1 - hm2, lg.y);   // u'(-1)
        float v0  = fmaf(-HL, h0 - hm1, u0);
        float v1  = fmaf(-HL, h1 - h0,  u1);
        float v2  = fmaf(-HL, h2 - h1,  u2);
        float v3  = fmaf(-HL, h3 - h2,  u3);
        float v4  = fmaf(-HL, h4 - h3,  rg.x);    // u'(4)

        // mid-fusion outflow BC (reference applies BC every step)
        if (e0) v0 = v1;
        if (e1) v3 = v2;
        // (vm1 / v4 are garbage at the global edges; they only feed k0 / k4,
        //  whose targets w0 / w3 are overwritten by the BC below.)

        // frame 2it+1
        __stcs(op, make_float4(v0, v1, v2, v3));

        // ========== step B: f,|f'| on u'(-1..4) (3 packs) ==========
        float gm, gp, bm, bp, g0, g1, b0, b1, g2, g3, b2, b3;
        { u64 U = pk(vm1, v4); POLY_PACK(U, gm, gp, bm, bp); }
        { u64 U = pk(v0, v1);  POLY_PACK(U, g0, g1, b0, b1); }
        { u64 U = pk(v2, v3);  POLY_PACK(U, g2, g3, b2, b3); }

        float k0 = iface(vm1, gm, bm, v0, g0, b0);
        float k1 = iface(v0, g0, b0, v1, g1, b1);
        float k2 = iface(v1, g1, b1, v2, g2, b2);
        float k3 = iface(v2, g2, b2, v3, g3, b3);
        float k4 = iface(v3, g3, b3, v4, gp, bp);

        float w0 = fmaf(-HL, k1 - k0, v0);
        float w1 = fmaf(-HL, k2 - k1, v1);
        float w2 = fmaf(-HL, k3 - k2, v2);
        float w3 = fmaf(-HL, k4 - k3, v3);
        if (e0) w0 = w1;
        if (e1) w3 = w2;

        // publish boundaries for the next fused iter (other buffer)
        const int np = p ^ 1;
        sL[np][tid] = make_float2(w0, w1);
        sR[np][tid] = make_float2(w2, w3);

        // frame 2it+2
        __stcs(op + ostride, make_float4(w0, w1, w2, w3));
        op += 2 * ostride;

        u0 = w0; u1 = w1; u2 = w2; u3 = w3;
        p = np;
    }

    // ========== tail: single step 255 (R7 style) ==========
    __syncthreads();
    float um = sR[p][tl].y;   // u(base-1)
    float up = sL[p][tr].x;   // u(base+4)

    float f0, f1, a0, a1, f2, f3, a2, a3, fm, fp, am, ap;
    { u64 U = pk(u0, u1); POLY_PACK(U, f0, f1, a0, a1); }
    { u64 U = pk(u2, u3); POLY_PACK(U, f2, f3, a2, a3); }
    { u64 U = pk(um, up); POLY_PACK(U, fm, fp, am, ap); }

    float h0 = iface(um, fm, am, u0, f0, a0);
    float h1 = iface(u0, f0, a0, u1, f1, a1);
    float h2 = iface(u1, f1, a1, u2, f2, a2);
    float h3 = iface(u2, f2, a2, u3, f3, a3);
    float h4 = iface(u3, f3, a3, up, fp, ap);

    float w0 = fmaf(-HL, h1 - h0, u0);
    float w1 = fmaf(-HL, h2 - h1, u1);
    float w2 = fmaf(-HL, h3 - h2, u2);
    float w3 = fmaf(-HL, h4 - h3, u3);
    if (e0) w0 = w1;
    if (e1) w3 = w2;

    __stcs(op, make_float4(w0, w1, w2, w3));
}

extern "C" void kernel_launch(void* const* d_in, const int* in_sizes, int n_in,
                              void* d_out, int out_size) {
    const float* init = (const float*)d_in[0];   // [128, 2048] fp32
    // d_in[1] = stepnum (int32) — fixed at 256 by the problem spec
    float* out = (float*)d_out;                  // [256, 128, 2048] fp32
    vcl_kernel<<<BATCH, TPB>>>(init, out);
}